// round 2
// baseline (speedup 1.0000x reference)
#include <cuda_runtime.h>

// HJB loss, single-kernel version with last-block-done final reduction.
//
// Per-row math (constants folded from reference):
//   xr = X - (1,0,0,0)
//   dyn0 = X2 + 0.3*u0
//   dyn1 = X3 + 0.25*u1
//   dyn2 = 0.6*X1 + u0 + 0.5*mu0
//   dyn3 = -0.6*X0 + u1 + 0.5*mu1
//   g    = 2*(xr0*dyn0 + xr1*dyn1) + xr2*dyn2 + xr3*dyn3     (2*xr^T Q dyn)
//   V    = xr0^2 + xr1^2 + 0.5*(xr2^2 + xr3^2)
//   uRu  = 0.05*(u0^2 + u1^2)
//   tr   = 0.25*sigma^2           (trace(2Q @ COV COV^T) = 0.5)
//   loss = mean(g + V + uRu + tr)

#define RBLOCKS 2048
#define RTHREADS 256

__device__ float g_partials[RBLOCKS];
__device__ unsigned int g_done_count;  // zero-initialized; last block resets to 0

__global__ __launch_bounds__(RTHREADS)
void hjb_fused(const float4* __restrict__ X,
               const float2* __restrict__ mu,
               const float*  __restrict__ sigma,
               const float2* __restrict__ u,
               float* __restrict__ out,
               int B)
{
    const int tid    = blockIdx.x * blockDim.x + threadIdx.x;
    const int stride = gridDim.x * blockDim.x;

    float acc = 0.0f;

    for (int i = tid; i < B; i += stride) {
        float4 x  = X[i];
        float2 m  = mu[i];
        float2 uu = u[i];
        float  sg = sigma[i];

        float xr0 = x.x - 1.0f;
        float xr1 = x.y;
        float xr2 = x.z;
        float xr3 = x.w;

        float dyn0 = fmaf(0.3f,  uu.x, x.z);
        float dyn1 = fmaf(0.25f, uu.y, x.w);
        float dyn2 = fmaf(0.6f,  x.y, uu.x) + 0.5f * m.x;
        float dyn3 = fmaf(-0.6f, x.x, uu.y) + 0.5f * m.y;

        float g = 2.0f * (xr0 * dyn0 + xr1 * dyn1) + xr2 * dyn2 + xr3 * dyn3;
        float V = xr0 * xr0 + xr1 * xr1 + 0.5f * (xr2 * xr2 + xr3 * xr3);
        float uRu = 0.05f * (uu.x * uu.x + uu.y * uu.y);
        float tr  = 0.25f * sg * sg;

        acc += g + V + uRu + tr;
    }

    // ── block reduce (float) ──
    #pragma unroll
    for (int off = 16; off > 0; off >>= 1)
        acc += __shfl_xor_sync(0xFFFFFFFFu, acc, off);

    __shared__ float s_warp[RTHREADS / 32];
    const int lane = threadIdx.x & 31;
    const int wid  = threadIdx.x >> 5;
    if (lane == 0) s_warp[wid] = acc;
    __syncthreads();

    __shared__ bool s_is_last;
    if (threadIdx.x == 0) {
        float v = 0.0f;
        #pragma unroll
        for (int w = 0; w < RTHREADS / 32; w++) v += s_warp[w];
        g_partials[blockIdx.x] = v;
        __threadfence();
        unsigned int prev = atomicAdd(&g_done_count, 1u);
        s_is_last = (prev == (unsigned int)(gridDim.x - 1));
    }
    __syncthreads();

    // ── last block: deterministic final reduce in double ──
    if (s_is_last) {
        const int t = threadIdx.x;
        double v = 0.0;
        #pragma unroll
        for (int j = 0; j < RBLOCKS / RTHREADS; j++)
            v += (double)g_partials[t + j * RTHREADS];

        // tree-reduce doubles via shared
        __shared__ double sd[RTHREADS];
        sd[t] = v;
        __syncthreads();
        #pragma unroll
        for (int off = RTHREADS / 2; off >= 32; off >>= 1) {
            if (t < off) sd[t] += sd[t + off];
            __syncthreads();
        }
        if (t < 32) {
            double w = sd[t];
            #pragma unroll
            for (int off = 16; off > 0; off >>= 1) {
                // shuffle doubles via two 32-bit halves
                unsigned long long bits = __double_as_longlong(w);
                unsigned int lo = (unsigned int)(bits & 0xFFFFFFFFull);
                unsigned int hi = (unsigned int)(bits >> 32);
                lo = __shfl_xor_sync(0xFFFFFFFFu, lo, off);
                hi = __shfl_xor_sync(0xFFFFFFFFu, hi, off);
                w += __longlong_as_double(((unsigned long long)hi << 32) | lo);
            }
            if (t == 0) {
                out[0] = (float)(w / (double)B);
                g_done_count = 0;  // reset for next graph replay
            }
        }
    }
}

extern "C" void kernel_launch(void* const* d_in, const int* in_sizes, int n_in,
                              void* d_out, int out_size)
{
    const float4* X     = (const float4*)d_in[0];
    const float2* mu    = (const float2*)d_in[1];
    const float*  sigma = (const float*) d_in[2];
    const float2* u     = (const float2*)d_in[3];
    float* out = (float*)d_out;

    int B = in_sizes[2];  // sigma has B elements

    hjb_fused<<<RBLOCKS, RTHREADS>>>(X, mu, sigma, u, out, B);
}

// round 3
// speedup vs baseline: 1.1395x; 1.1395x over previous
#include <cuda_runtime.h>

// HJB loss, single kernel, unroll-4 batched loads for MLP, last-block-done reduce.
//
// Per-row math (constants folded from reference):
//   xr = X - (1,0,0,0)
//   dyn0 = X2 + 0.3*u0 ; dyn1 = X3 + 0.25*u1
//   dyn2 = 0.6*X1 + u0 + 0.5*mu0 ; dyn3 = -0.6*X0 + u1 + 0.5*mu1
//   s = 2*(xr0*dyn0 + xr1*dyn1) + xr2*dyn2 + xr3*dyn3
//     + xr0^2 + xr1^2 + 0.5*(xr2^2+xr3^2) + 0.05*(u0^2+u1^2) + 0.25*sigma^2
//   loss = mean(s)

#define RBLOCKS 2048
#define RTHREADS 256

__device__ float g_partials[RBLOCKS];
__device__ unsigned int g_done_count;  // zero-init; last block resets to 0

__device__ __forceinline__ float row_term(float4 x, float2 m, float2 uu, float sg)
{
    float xr0 = x.x - 1.0f;
    float xr1 = x.y;
    float xr2 = x.z;
    float xr3 = x.w;

    float dyn0 = fmaf(0.3f,  uu.x, x.z);
    float dyn1 = fmaf(0.25f, uu.y, x.w);
    float dyn2 = fmaf(0.6f,  x.y, uu.x) + 0.5f * m.x;
    float dyn3 = fmaf(-0.6f, x.x, uu.y) + 0.5f * m.y;

    float g = 2.0f * (xr0 * dyn0 + xr1 * dyn1) + xr2 * dyn2 + xr3 * dyn3;
    float V = xr0 * xr0 + xr1 * xr1 + 0.5f * (xr2 * xr2 + xr3 * xr3);
    float uRu = 0.05f * (uu.x * uu.x + uu.y * uu.y);
    float tr  = 0.25f * sg * sg;
    return g + V + uRu + tr;
}

__global__ __launch_bounds__(RTHREADS)
void hjb_fused(const float4* __restrict__ X,
               const float2* __restrict__ mu,
               const float*  __restrict__ sigma,
               const float2* __restrict__ u,
               float* __restrict__ out,
               int B)
{
    const int tid    = blockIdx.x * blockDim.x + threadIdx.x;
    const int stride = gridDim.x * blockDim.x;

    float a0 = 0.0f, a1 = 0.0f, a2 = 0.0f, a3 = 0.0f;

    int i = tid;
    // unroll-4 main loop: 16 independent loads batched per iteration
    for (; i + 3 * stride < B; i += 4 * stride) {
        const int i0 = i;
        const int i1 = i + stride;
        const int i2 = i + 2 * stride;
        const int i3 = i + 3 * stride;

        float4 x0 = X[i0], x1 = X[i1], x2 = X[i2], x3 = X[i3];
        float2 m0 = mu[i0], m1 = mu[i1], m2 = mu[i2], m3 = mu[i3];
        float2 u0 = u[i0],  u1 = u[i1],  u2 = u[i2],  u3 = u[i3];
        float  s0 = sigma[i0], s1 = sigma[i1], s2 = sigma[i2], s3 = sigma[i3];

        a0 += row_term(x0, m0, u0, s0);
        a1 += row_term(x1, m1, u1, s1);
        a2 += row_term(x2, m2, u2, s2);
        a3 += row_term(x3, m3, u3, s3);
    }
    // remainder
    for (; i < B; i += stride)
        a0 += row_term(X[i], mu[i], u[i], sigma[i]);

    float acc = (a0 + a1) + (a2 + a3);

    // ── block reduce (float) ──
    #pragma unroll
    for (int off = 16; off > 0; off >>= 1)
        acc += __shfl_xor_sync(0xFFFFFFFFu, acc, off);

    __shared__ float s_warp[RTHREADS / 32];
    const int lane = threadIdx.x & 31;
    const int wid  = threadIdx.x >> 5;
    if (lane == 0) s_warp[wid] = acc;
    __syncthreads();

    __shared__ bool s_is_last;
    if (threadIdx.x == 0) {
        float v = 0.0f;
        #pragma unroll
        for (int w = 0; w < RTHREADS / 32; w++) v += s_warp[w];
        g_partials[blockIdx.x] = v;
        __threadfence();
        unsigned int prev = atomicAdd(&g_done_count, 1u);
        s_is_last = (prev == (unsigned int)(gridDim.x - 1));
    }
    __syncthreads();

    // ── last block: deterministic final reduce in double ──
    if (s_is_last) {
        const int t = threadIdx.x;
        double v = 0.0;
        #pragma unroll
        for (int j = 0; j < RBLOCKS / RTHREADS; j++)
            v += (double)g_partials[t + j * RTHREADS];

        __shared__ double sd[RTHREADS];
        sd[t] = v;
        __syncthreads();
        #pragma unroll
        for (int off = RTHREADS / 2; off >= 32; off >>= 1) {
            if (t < off) sd[t] += sd[t + off];
            __syncthreads();
        }
        if (t < 32) {
            double w = sd[t];
            #pragma unroll
            for (int off = 16; off > 0; off >>= 1) {
                unsigned long long bits = __double_as_longlong(w);
                unsigned int lo = (unsigned int)(bits & 0xFFFFFFFFull);
                unsigned int hi = (unsigned int)(bits >> 32);
                lo = __shfl_xor_sync(0xFFFFFFFFu, lo, off);
                hi = __shfl_xor_sync(0xFFFFFFFFu, hi, off);
                w += __longlong_as_double(((unsigned long long)hi << 32) | lo);
            }
            if (t == 0) {
                out[0] = (float)(w / (double)B);
                g_done_count = 0;  // reset for next graph replay
            }
        }
    }
}

extern "C" void kernel_launch(void* const* d_in, const int* in_sizes, int n_in,
                              void* d_out, int out_size)
{
    const float4* X     = (const float4*)d_in[0];
    const float2* mu    = (const float2*)d_in[1];
    const float*  sigma = (const float*) d_in[2];
    const float2* u     = (const float2*)d_in[3];
    float* out = (float*)d_out;

    int B = in_sizes[2];  // sigma has B elements

    hjb_fused<<<RBLOCKS, RTHREADS>>>(X, mu, sigma, u, out, B);
}

// round 4
// speedup vs baseline: 1.1707x; 1.0274x over previous
#include <cuda_runtime.h>

// HJB loss. One kernel, one wave (592 = 4*148 blocks), all-LDG.128 streaming
// loads (4 consecutive rows per group per thread), last-block-done reduction.
//
// Per-row math (constants folded from reference):
//   xr = X - (1,0,0,0)
//   dyn0 = X2 + 0.3*u0 ; dyn1 = X3 + 0.25*u1
//   dyn2 = 0.6*X1 + u0 + 0.5*mu0 ; dyn3 = -0.6*X0 + u1 + 0.5*mu1
//   s = 2*(xr0*dyn0 + xr1*dyn1) + xr2*dyn2 + xr3*dyn3
//     + xr0^2 + xr1^2 + 0.5*(xr2^2+xr3^2) + 0.05*(u0^2+u1^2) + 0.25*sigma^2
//   loss = mean(s);  trace(2Q @ COV COV^T) = 0.5 -> 0.25*sigma^2 term.

#define RBLOCKS 592   // 4 * 148 SMs -> exactly one wave at 4 blocks/SM
#define RTHREADS 256

__device__ float g_partials[RBLOCKS];
__device__ unsigned int g_done_count;  // zero-init; last block resets to 0

__device__ __forceinline__ float row_term(float4 x, float mx, float my,
                                          float ux, float uy, float sg)
{
    float xr0 = x.x - 1.0f;
    float xr1 = x.y;
    float xr2 = x.z;
    float xr3 = x.w;

    float dyn0 = fmaf(0.3f,  ux, x.z);
    float dyn1 = fmaf(0.25f, uy, x.w);
    float dyn2 = fmaf(0.6f,  x.y, ux) + 0.5f * mx;
    float dyn3 = fmaf(-0.6f, x.x, uy) + 0.5f * my;

    float g = 2.0f * (xr0 * dyn0 + xr1 * dyn1) + xr2 * dyn2 + xr3 * dyn3;
    float V = xr0 * xr0 + xr1 * xr1 + 0.5f * (xr2 * xr2 + xr3 * xr3);
    float uRu = 0.05f * (ux * ux + uy * uy);
    float tr  = 0.25f * sg * sg;
    return g + V + uRu + tr;
}

// process one group of 4 consecutive rows starting at row 4*g
__device__ __forceinline__ float group_term(const float4* __restrict__ X,
                                            const float4* __restrict__ MU,
                                            const float4* __restrict__ SG,
                                            const float4* __restrict__ U,
                                            int g)
{
    float4 x0 = __ldcs(X + 4 * g + 0);
    float4 x1 = __ldcs(X + 4 * g + 1);
    float4 x2 = __ldcs(X + 4 * g + 2);
    float4 x3 = __ldcs(X + 4 * g + 3);
    float4 m0 = __ldcs(MU + 2 * g + 0);   // rows 4g, 4g+1
    float4 m1 = __ldcs(MU + 2 * g + 1);   // rows 4g+2, 4g+3
    float4 u0 = __ldcs(U + 2 * g + 0);
    float4 u1 = __ldcs(U + 2 * g + 1);
    float4 sg = __ldcs(SG + g);           // 4 sigmas

    float t0 = row_term(x0, m0.x, m0.y, u0.x, u0.y, sg.x);
    float t1 = row_term(x1, m0.z, m0.w, u0.z, u0.w, sg.y);
    float t2 = row_term(x2, m1.x, m1.y, u1.x, u1.y, sg.z);
    float t3 = row_term(x3, m1.z, m1.w, u1.z, u1.w, sg.w);
    return (t0 + t1) + (t2 + t3);
}

__global__ __launch_bounds__(RTHREADS, 4)
void hjb_fused(const float4* __restrict__ X,
               const float4* __restrict__ MU,
               const float*  __restrict__ sigma,
               const float4* __restrict__ U,
               float* __restrict__ out,
               int B)
{
    const float4* SG = (const float4*)sigma;

    const int tid    = blockIdx.x * blockDim.x + threadIdx.x;
    const int stride = gridDim.x * blockDim.x;
    const int nG     = B >> 2;   // groups of 4 rows

    float a0 = 0.0f, a1 = 0.0f;

    int g = tid;
    // unroll-2 over groups: 18 independent LDG.128 batched per iteration
    for (; g + stride < nG; g += 2 * stride) {
        a0 += group_term(X, MU, SG, U, g);
        a1 += group_term(X, MU, SG, U, g + stride);
    }
    for (; g < nG; g += stride)
        a0 += group_term(X, MU, SG, U, g);

    float acc = a0 + a1;

    // scalar tail rows (B % 4) handled by thread 0 of block 0
    if (blockIdx.x == 0 && threadIdx.x == 0) {
        const float* Xs  = (const float*)X;
        const float* MUs = (const float*)MU;
        const float* Us  = (const float*)U;
        for (int r = nG * 4; r < B; r++) {
            float4 x = make_float4(Xs[4*r], Xs[4*r+1], Xs[4*r+2], Xs[4*r+3]);
            acc += row_term(x, MUs[2*r], MUs[2*r+1], Us[2*r], Us[2*r+1], sigma[r]);
        }
    }

    // ── block reduce (float) ──
    #pragma unroll
    for (int off = 16; off > 0; off >>= 1)
        acc += __shfl_xor_sync(0xFFFFFFFFu, acc, off);

    __shared__ float s_warp[RTHREADS / 32];
    const int lane = threadIdx.x & 31;
    const int wid  = threadIdx.x >> 5;
    if (lane == 0) s_warp[wid] = acc;
    __syncthreads();

    __shared__ bool s_is_last;
    if (threadIdx.x == 0) {
        float v = 0.0f;
        #pragma unroll
        for (int w = 0; w < RTHREADS / 32; w++) v += s_warp[w];
        g_partials[blockIdx.x] = v;
        __threadfence();
        unsigned int prev = atomicAdd(&g_done_count, 1u);
        s_is_last = (prev == (unsigned int)(gridDim.x - 1));
    }
    __syncthreads();

    // ── last block: deterministic final reduce in double ──
    if (s_is_last) {
        const int t = threadIdx.x;
        double v = 0.0;
        #pragma unroll
        for (int j = 0; j < (RBLOCKS + RTHREADS - 1) / RTHREADS; j++) {
            int idx = t + j * RTHREADS;
            if (idx < RBLOCKS) v += (double)g_partials[idx];
        }

        __shared__ double sd[RTHREADS];
        sd[t] = v;
        __syncthreads();
        #pragma unroll
        for (int off = RTHREADS / 2; off >= 32; off >>= 1) {
            if (t < off) sd[t] += sd[t + off];
            __syncthreads();
        }
        if (t < 32) {
            double w = sd[t];
            #pragma unroll
            for (int off = 16; off > 0; off >>= 1) {
                unsigned long long bits = __double_as_longlong(w);
                unsigned int lo = (unsigned int)(bits & 0xFFFFFFFFull);
                unsigned int hi = (unsigned int)(bits >> 32);
                lo = __shfl_xor_sync(0xFFFFFFFFu, lo, off);
                hi = __shfl_xor_sync(0xFFFFFFFFu, hi, off);
                w += __longlong_as_double(((unsigned long long)hi << 32) | lo);
            }
            if (t == 0) {
                out[0] = (float)(w / (double)B);
                g_done_count = 0;  // reset for next graph replay
            }
        }
    }
}

extern "C" void kernel_launch(void* const* d_in, const int* in_sizes, int n_in,
                              void* d_out, int out_size)
{
    const float4* X     = (const float4*)d_in[0];
    const float4* MU    = (const float4*)d_in[1];
    const float*  sigma = (const float*) d_in[2];
    const float4* U     = (const float4*)d_in[3];
    float* out = (float*)d_out;

    int B = in_sizes[2];  // sigma has B elements

    hjb_fused<<<RBLOCKS, RTHREADS>>>(X, MU, sigma, U, out, B);
}